// round 2
// baseline (speedup 1.0000x reference)
#include <cuda_runtime.h>
#include <cuda_bf16.h>
#include <cstdint>

// Problem constants
#define BATCH   2
#define SEQ     2048
#define DMODEL  1024
#define NHEADS  16
#define HDIM    64
#define MTOT    (BATCH * SEQ)          // 4096

// Scratch (device globals; no allocations allowed)
__device__ float g_Q[BATCH * NHEADS * SEQ * HDIM];     // [b,h,s,d]  16 MB
__device__ float g_K[BATCH * NHEADS * SEQ * HDIM];
__device__ float g_V[BATCH * NHEADS * SEQ * HDIM];
__device__ float g_attn[MTOT * DMODEL];                // [b*s, h*d] 16 MB

// ---------------------------------------------------------------------------
// GEMM: out[m][n] = X[m][:] @ W[:][n] + bias[n]
// M = 4096, K = 1024, N = 1024. Tile 64x64x16, 256 threads, 4x4 per thread.
// mode 0: scatter to head-major [b,h,s,d]; mode 1: plain row-major [m][n].
// ---------------------------------------------------------------------------
__global__ __launch_bounds__(256) void gemm_bias_kernel(
    const float* __restrict__ X, const float* __restrict__ W,
    const float* __restrict__ bias, float* __restrict__ out, int mode) {
    __shared__ float As[16][64];   // A transposed: [k][m]
    __shared__ float Bs[16][64];   // [k][n]

    const int tid = threadIdx.x;
    const int rg  = tid >> 4;      // 0..15 -> rows rg*4..+3
    const int cg  = tid & 15;      // 0..15 -> cols cg*4..+3
    const int m0  = blockIdx.y * 64;
    const int n0  = blockIdx.x * 64;

    const int la_row = tid >> 2;        // 0..63
    const int la_seg = (tid & 3) * 4;   // k segment
    const int lb_row = tid >> 4;        // 0..15
    const int lb_col = (tid & 15) * 4;  // n segment

    float acc[4][4] = {};

    for (int k0 = 0; k0 < DMODEL; k0 += 16) {
        float4 a4 = *(const float4*)(X + (size_t)(m0 + la_row) * DMODEL + k0 + la_seg);
        float4 b4 = *(const float4*)(W + (size_t)(k0 + lb_row) * DMODEL + n0 + lb_col);
        __syncthreads();
        As[la_seg + 0][la_row] = a4.x;
        As[la_seg + 1][la_row] = a4.y;
        As[la_seg + 2][la_row] = a4.z;
        As[la_seg + 3][la_row] = a4.w;
        *(float4*)&Bs[lb_row][lb_col] = b4;
        __syncthreads();
#pragma unroll
        for (int k = 0; k < 16; k++) {
            float4 a = *(const float4*)&As[k][rg * 4];
            float4 b = *(const float4*)&Bs[k][cg * 4];
            acc[0][0] += a.x * b.x; acc[0][1] += a.x * b.y; acc[0][2] += a.x * b.z; acc[0][3] += a.x * b.w;
            acc[1][0] += a.y * b.x; acc[1][1] += a.y * b.y; acc[1][2] += a.y * b.z; acc[1][3] += a.y * b.w;
            acc[2][0] += a.z * b.x; acc[2][1] += a.z * b.y; acc[2][2] += a.z * b.z; acc[2][3] += a.z * b.w;
            acc[3][0] += a.w * b.x; acc[3][1] += a.w * b.y; acc[3][2] += a.w * b.z; acc[3][3] += a.w * b.w;
        }
    }

    const int n_base = n0 + cg * 4;
    const float4 bb = *(const float4*)(bias + n_base);
#pragma unroll
    for (int i = 0; i < 4; i++) {
        const int m = m0 + rg * 4 + i;
        float4 r;
        r.x = acc[i][0] + bb.x;
        r.y = acc[i][1] + bb.y;
        r.z = acc[i][2] + bb.z;
        r.w = acc[i][3] + bb.w;
        if (mode == 0) {
            const int b = m >> 11, s = m & 2047;
            const int h = n_base >> 6, d = n_base & 63;
            *(float4*)(out + (((size_t)b * NHEADS + h) * SEQ + s) * HDIM + d) = r;
        } else {
            *(float4*)(out + (size_t)m * DMODEL + n_base) = r;
        }
    }
}

// ---------------------------------------------------------------------------
// Flash attention: one block per (q-tile of 64, head, batch). 256 threads.
// Q tile stays in smem; K tile and P (probs) share one buffer; V in its own.
// XOR swizzle on the float4-unit index breaks column-stride bank conflicts.
// Softmax stats reduced with shfl_xor over the 16 lanes owning each row group.
// ---------------------------------------------------------------------------
__global__ __launch_bounds__(256) void attn_kernel(
    const float* __restrict__ Q, const float* __restrict__ K,
    const float* __restrict__ V, float* __restrict__ Out) {
    __shared__ float Qs[64 * 64];
    __shared__ float KP[64 * 64];   // K tile, then reused for P
    __shared__ float Vs[64 * 64];

    const int tid = threadIdx.x;
    const int rg  = tid >> 4;       // row group 0..15
    const int cg  = tid & 15;       // col group 0..15
    const int q0  = blockIdx.x * 64;
    const int h   = blockIdx.y;
    const int b   = blockIdx.z;
    const size_t bh = (size_t)b * NHEADS + h;
    const float* Qb = Q + bh * SEQ * HDIM;
    const float* Kb = K + bh * SEQ * HDIM;
    const float* Vb = V + bh * SEQ * HDIM;

    float4* Qs4 = (float4*)Qs;
    float4* KP4 = (float4*)KP;
    float4* Vs4 = (float4*)Vs;

    // Load Q tile (swizzled: [r][x] -> r*16 + (x ^ (r>>2)))
#pragma unroll
    for (int i = 0; i < 4; i++) {
        const int idx = tid + i * 256;
        const int r = idx >> 4;
        const int x = idx & 15;
        float4 vq = *(const float4*)(Qb + (size_t)(q0 + r) * HDIM + x * 4);
        Qs4[r * 16 + (x ^ (r >> 2))] = vq;
    }

    float m_i[4], l_i[4], o[4][4];
#pragma unroll
    for (int i = 0; i < 4; i++) {
        m_i[i] = -1e30f;
        l_i[i] = 0.f;
#pragma unroll
        for (int j = 0; j < 4; j++) o[i][j] = 0.f;
    }

    for (int kt = 0; kt < SEQ; kt += 64) {
        __syncthreads();   // prev iter done reading Vs / P
#pragma unroll
        for (int i = 0; i < 4; i++) {
            const int idx = tid + i * 256;
            const int r = idx >> 4;
            const int x = idx & 15;
            float4 kv = *(const float4*)(Kb + (size_t)(kt + r) * HDIM + x * 4);
            KP4[r * 16 + (x ^ (r >> 2))] = kv;
            float4 vv = *(const float4*)(Vb + (size_t)(kt + r) * HDIM + x * 4);
            Vs4[r * 16 + (x ^ (r >> 2))] = vv;
        }
        __syncthreads();

        // S = Q K^T  (4x4 per thread)
        float s[4][4] = {};
#pragma unroll
        for (int d4 = 0; d4 < 16; d4++) {
            float4 qv[4], kv[4];
#pragma unroll
            for (int i = 0; i < 4; i++) qv[i] = Qs4[(rg * 4 + i) * 16 + (d4 ^ rg)];
#pragma unroll
            for (int j = 0; j < 4; j++) kv[j] = KP4[(cg * 4 + j) * 16 + (d4 ^ cg)];
#pragma unroll
            for (int i = 0; i < 4; i++)
#pragma unroll
                for (int j = 0; j < 4; j++)
                    s[i][j] += qv[i].x * kv[j].x + qv[i].y * kv[j].y +
                               qv[i].z * kv[j].z + qv[i].w * kv[j].w;
        }

#pragma unroll
        for (int i = 0; i < 4; i++)
#pragma unroll
            for (int j = 0; j < 4; j++) s[i][j] *= 0.125f;   // 1/sqrt(64)

        // Row max via shfl over the 16 lanes of this row group
        float pm[4];
#pragma unroll
        for (int i = 0; i < 4; i++)
            pm[i] = fmaxf(fmaxf(s[i][0], s[i][1]), fmaxf(s[i][2], s[i][3]));
#pragma unroll
        for (int off = 8; off; off >>= 1)
#pragma unroll
            for (int i = 0; i < 4; i++)
                pm[i] = fmaxf(pm[i], __shfl_xor_sync(0xffffffffu, pm[i], off, 32));

        float p[4][4], m_new[4], rs[4];
#pragma unroll
        for (int i = 0; i < 4; i++) {
            m_new[i] = fmaxf(m_i[i], pm[i]);
            rs[i] = 0.f;
#pragma unroll
            for (int j = 0; j < 4; j++) {
                p[i][j] = __expf(s[i][j] - m_new[i]);
                rs[i] += p[i][j];
            }
        }
#pragma unroll
        for (int off = 8; off; off >>= 1)
#pragma unroll
            for (int i = 0; i < 4; i++)
                rs[i] += __shfl_xor_sync(0xffffffffu, rs[i], off, 32);

#pragma unroll
        for (int i = 0; i < 4; i++) {
            const float alpha = __expf(m_i[i] - m_new[i]);
            l_i[i] = l_i[i] * alpha + rs[i];
            m_i[i] = m_new[i];
#pragma unroll
            for (int j = 0; j < 4; j++) o[i][j] *= alpha;
        }

        __syncthreads();   // all QK reads of KP done
#pragma unroll
        for (int i = 0; i < 4; i++) {
            float4 pv = make_float4(p[i][0], p[i][1], p[i][2], p[i][3]);
            KP4[(rg * 4 + i) * 16 + (cg ^ rg)] = pv;   // P[r=rg*4+i][cols cg*4..+3]
        }
        __syncthreads();

        // O += P @ V
#pragma unroll
        for (int k4 = 0; k4 < 16; k4++) {
            float4 pp[4];
#pragma unroll
            for (int i = 0; i < 4; i++) pp[i] = KP4[(rg * 4 + i) * 16 + (k4 ^ rg)];
#pragma unroll
            for (int kk = 0; kk < 4; kk++) {
                float4 vrow = Vs4[(k4 * 4 + kk) * 16 + (cg ^ k4)];
#pragma unroll
                for (int i = 0; i < 4; i++) {
                    const float pi = ((const float*)&pp[i])[kk];
                    o[i][0] += pi * vrow.x;
                    o[i][1] += pi * vrow.y;
                    o[i][2] += pi * vrow.z;
                    o[i][3] += pi * vrow.w;
                }
            }
        }
    }

    // Epilogue: normalize, write to [b*s][h*64+d]
#pragma unroll
    for (int i = 0; i < 4; i++) {
        const float inv = 1.0f / l_i[i];
        float4 r = make_float4(o[i][0] * inv, o[i][1] * inv, o[i][2] * inv, o[i][3] * inv);
        const int q = q0 + rg * 4 + i;
        *(float4*)(Out + ((size_t)b * SEQ + q) * DMODEL + h * HDIM + cg * 4) = r;
    }
}

// ---------------------------------------------------------------------------
extern "C" void kernel_launch(void* const* d_in, const int* in_sizes, int n_in,
                              void* d_out, int out_size) {
    const float* q  = (const float*)d_in[0];
    const float* k  = (const float*)d_in[1];
    const float* v  = (const float*)d_in[2];
    const float* Wq = (const float*)d_in[3];
    const float* bq = (const float*)d_in[4];
    const float* Wk = (const float*)d_in[5];
    const float* bk = (const float*)d_in[6];
    const float* Wv = (const float*)d_in[7];
    const float* bv = (const float*)d_in[8];
    const float* Wo = (const float*)d_in[9];
    const float* bo = (const float*)d_in[10];
    float* out = (float*)d_out;

    float *gq, *gk, *gv, *ga;
    cudaGetSymbolAddress((void**)&gq, g_Q);
    cudaGetSymbolAddress((void**)&gk, g_K);
    cudaGetSymbolAddress((void**)&gv, g_V);
    cudaGetSymbolAddress((void**)&ga, g_attn);

    dim3 gemm_grid(DMODEL / 64, MTOT / 64);   // (16, 64)
    dim3 block(256);

    gemm_bias_kernel<<<gemm_grid, block>>>(q, Wq, bq, gq, 0);
    gemm_bias_kernel<<<gemm_grid, block>>>(k, Wk, bk, gk, 0);
    gemm_bias_kernel<<<gemm_grid, block>>>(v, Wv, bv, gv, 0);

    dim3 attn_grid(SEQ / 64, NHEADS, BATCH);  // (32, 16, 2)
    attn_kernel<<<attn_grid, block>>>(gq, gk, gv, ga);

    gemm_bias_kernel<<<gemm_grid, block>>>(ga, Wo, bo, out, 1);
}

// round 6
// speedup vs baseline: 1.5586x; 1.5586x over previous
#include <cuda_runtime.h>
#include <cuda_bf16.h>
#include <cstdint>

// Problem constants
#define BATCH   2
#define SEQ     2048
#define DMODEL  1024
#define NHEADS  16
#define HDIM    64
#define MTOT    (BATCH * SEQ)          // 4096

// Scratch (device globals; no allocations allowed)
__device__ float g_Q[BATCH * NHEADS * SEQ * HDIM];     // [b,h,s,d]  16 MB
__device__ float g_K[BATCH * NHEADS * SEQ * HDIM];
__device__ float g_V[BATCH * NHEADS * SEQ * HDIM];
__device__ float g_attn[MTOT * DMODEL];                // [b*s, h*d] 16 MB

__device__ __forceinline__ uint32_t f2tf32(float f) {
    uint32_t r;
    asm("cvt.rna.tf32.f32 %0, %1;" : "=r"(r) : "f"(f));
    return r;
}

// ---------------------------------------------------------------------------
// tf32 tensor-core GEMM: out[m][n] = X[m][:] @ W[:][n] + bias[n]
// M=4096, K=1024, N=1024. Block tile 128x128x16, 256 threads (8 warps, 4x2),
// warp tile 32x64 via m16n8k8 tf32 mma. Double-buffered smem, 1 sync/iter.
// A smem [m][k] stride 20 (frag loads conflict-free: bank=20g+t);
// B smem [k][n] stride 136 (frag loads conflict-free: bank=8t+g).
// mode 0: scatter to head-major [b,h,s,d]; mode 1: row-major [m][n].
// ---------------------------------------------------------------------------
#define SA 20
#define SB 136

__global__ __launch_bounds__(256, 2) void gemm_tf32_kernel(
    const float* __restrict__ X, const float* __restrict__ W,
    const float* __restrict__ bias, float* __restrict__ out, int mode) {
    __shared__ uint32_t As[2][128][SA];   // [m][k]
    __shared__ uint32_t Bs[2][16][SB];    // [k][n]

    const int tid  = threadIdx.x;
    const int lane = tid & 31;
    const int warp = tid >> 5;
    const int g = lane >> 2;      // 0..7
    const int t = lane & 3;       // 0..3
    const int wm = (warp >> 1) * 32;
    const int wn = (warp & 1) * 64;
    const int m0 = blockIdx.y * 128;
    const int n0 = blockIdx.x * 128;

    // Staging-load mapping (two chunks of 256)
    // A: idx -> m = idx>>2 (0..127), kseg = (idx&3)*4    (coalesced 64B/4 lanes)
    const int am[2]  = { tid >> 2, (tid + 256) >> 2 };
    const int ak[2]  = { (tid & 3) * 4, (tid & 3) * 4 };
    // B: idx -> kB = idx>>5 (0..15), nB = (idx&31)*4     (coalesced 512B rows)
    const int bk[2]  = { tid >> 5, (tid + 256) >> 5 };
    const int bn[2]  = { (tid & 31) * 4, (tid & 31) * 4 };

    const float* Xp = X + (size_t)m0 * DMODEL;
    const float* Wp = W + n0;

    float c[2][8][4];
#pragma unroll
    for (int mt = 0; mt < 2; mt++)
#pragma unroll
        for (int ni = 0; ni < 8; ni++)
#pragma unroll
            for (int r = 0; r < 4; r++) c[mt][ni][r] = 0.f;

    float4 ra[2], rb[2];

    // Preload tile 0
#pragma unroll
    for (int i = 0; i < 2; i++) {
        ra[i] = *(const float4*)(Xp + (size_t)am[i] * DMODEL + ak[i]);
        rb[i] = *(const float4*)(Wp + (size_t)bk[i] * DMODEL + bn[i]);
    }
#pragma unroll
    for (int i = 0; i < 2; i++) {
        uint32_t* ap = &As[0][am[i]][ak[i]];
        ap[0] = f2tf32(ra[i].x); ap[1] = f2tf32(ra[i].y);
        ap[2] = f2tf32(ra[i].z); ap[3] = f2tf32(ra[i].w);
        uint32_t* bp = &Bs[0][bk[i]][bn[i]];
        bp[0] = f2tf32(rb[i].x); bp[1] = f2tf32(rb[i].y);
        bp[2] = f2tf32(rb[i].z); bp[3] = f2tf32(rb[i].w);
    }
    __syncthreads();

    int buf = 0;
    const int NITER = DMODEL / 16;   // 64
    for (int it = 0; it < NITER; it++) {
        const int k_next = (it + 1) * 16;
        if (it + 1 < NITER) {
#pragma unroll
            for (int i = 0; i < 2; i++) {
                ra[i] = *(const float4*)(Xp + (size_t)am[i] * DMODEL + k_next + ak[i]);
                rb[i] = *(const float4*)(Wp + (size_t)(k_next + bk[i]) * DMODEL + bn[i]);
            }
        }

        // Compute on smem[buf]
#pragma unroll
        for (int ks = 0; ks < 2; ks++) {
            const int kk = ks * 8;
            uint32_t a[2][4];
#pragma unroll
            for (int mt = 0; mt < 2; mt++) {
                const int row = wm + mt * 16 + g;
                a[mt][0] = As[buf][row    ][kk + t];
                a[mt][1] = As[buf][row + 8][kk + t];
                a[mt][2] = As[buf][row    ][kk + t + 4];
                a[mt][3] = As[buf][row + 8][kk + t + 4];
            }
#pragma unroll
            for (int ni = 0; ni < 8; ni++) {
                const uint32_t b0 = Bs[buf][kk + t    ][wn + ni * 8 + g];
                const uint32_t b1 = Bs[buf][kk + t + 4][wn + ni * 8 + g];
#pragma unroll
                for (int mt = 0; mt < 2; mt++) {
                    asm volatile(
                        "mma.sync.aligned.m16n8k8.row.col.f32.tf32.tf32.f32 "
                        "{%0,%1,%2,%3}, {%4,%5,%6,%7}, {%8,%9}, {%0,%1,%2,%3};"
                        : "+f"(c[mt][ni][0]), "+f"(c[mt][ni][1]),
                          "+f"(c[mt][ni][2]), "+f"(c[mt][ni][3])
                        : "r"(a[mt][0]), "r"(a[mt][1]), "r"(a[mt][2]), "r"(a[mt][3]),
                          "r"(b0), "r"(b1));
                }
            }
        }

        if (it + 1 < NITER) {
            const int nb = buf ^ 1;
#pragma unroll
            for (int i = 0; i < 2; i++) {
                uint32_t* ap = &As[nb][am[i]][ak[i]];
                ap[0] = f2tf32(ra[i].x); ap[1] = f2tf32(ra[i].y);
                ap[2] = f2tf32(ra[i].z); ap[3] = f2tf32(ra[i].w);
                uint32_t* bp = &Bs[nb][bk[i]][bn[i]];
                bp[0] = f2tf32(rb[i].x); bp[1] = f2tf32(rb[i].y);
                bp[2] = f2tf32(rb[i].z); bp[3] = f2tf32(rb[i].w);
            }
            __syncthreads();
            buf = nb;
        }
    }

    // Epilogue: bias add + store (float2 per fragment row)
#pragma unroll
    for (int ni = 0; ni < 8; ni++) {
        const int col = n0 + wn + ni * 8 + 2 * t;
        const float2 bb = *(const float2*)(bias + col);
#pragma unroll
        for (int mt = 0; mt < 2; mt++) {
            const int row0 = m0 + wm + mt * 16 + g;
#pragma unroll
            for (int half = 0; half < 2; half++) {
                const int m = row0 + half * 8;
                float2 r;
                r.x = c[mt][ni][half * 2 + 0] + bb.x;
                r.y = c[mt][ni][half * 2 + 1] + bb.y;
                if (mode == 0) {
                    const int b = m >> 11, s = m & 2047;
                    const int h = col >> 6, d = col & 63;
                    *(float2*)(out + (((size_t)b * NHEADS + h) * SEQ + s) * HDIM + d) = r;
                } else {
                    *(float2*)(out + (size_t)m * DMODEL + col) = r;
                }
            }
        }
    }
}

// ---------------------------------------------------------------------------
// Flash attention: one block per (q-tile of 64, head, batch). 256 threads.
// (unchanged — fp32 SIMT; tensor-core port gated on this round's rel_err)
// ---------------------------------------------------------------------------
__global__ __launch_bounds__(256) void attn_kernel(
    const float* __restrict__ Q, const float* __restrict__ K,
    const float* __restrict__ V, float* __restrict__ Out) {
    __shared__ float Qs[64 * 64];
    __shared__ float KP[64 * 64];   // K tile, then reused for P
    __shared__ float Vs[64 * 64];

    const int tid = threadIdx.x;
    const int rg  = tid >> 4;       // row group 0..15
    const int cg  = tid & 15;       // col group 0..15
    const int q0  = blockIdx.x * 64;
    const int h   = blockIdx.y;
    const int b   = blockIdx.z;
    const size_t bh = (size_t)b * NHEADS + h;
    const float* Qb = Q + bh * SEQ * HDIM;
    const float* Kb = K + bh * SEQ * HDIM;
    const float* Vb = V + bh * SEQ * HDIM;

    float4* Qs4 = (float4*)Qs;
    float4* KP4 = (float4*)KP;
    float4* Vs4 = (float4*)Vs;

#pragma unroll
    for (int i = 0; i < 4; i++) {
        const int idx = tid + i * 256;
        const int r = idx >> 4;
        const int x = idx & 15;
        float4 vq = *(const float4*)(Qb + (size_t)(q0 + r) * HDIM + x * 4);
        Qs4[r * 16 + (x ^ (r >> 2))] = vq;
    }

    float m_i[4], l_i[4], o[4][4];
#pragma unroll
    for (int i = 0; i < 4; i++) {
        m_i[i] = -1e30f;
        l_i[i] = 0.f;
#pragma unroll
        for (int j = 0; j < 4; j++) o[i][j] = 0.f;
    }

    for (int kt = 0; kt < SEQ; kt += 64) {
        __syncthreads();
#pragma unroll
        for (int i = 0; i < 4; i++) {
            const int idx = tid + i * 256;
            const int r = idx >> 4;
            const int x = idx & 15;
            float4 kv = *(const float4*)(Kb + (size_t)(kt + r) * HDIM + x * 4);
            KP4[r * 16 + (x ^ (r >> 2))] = kv;
            float4 vv = *(const float4*)(Vb + (size_t)(kt + r) * HDIM + x * 4);
            Vs4[r * 16 + (x ^ (r >> 2))] = vv;
        }
        __syncthreads();

        float s[4][4] = {};
#pragma unroll
        for (int d4 = 0; d4 < 16; d4++) {
            float4 qv[4], kv[4];
#pragma unroll
            for (int i = 0; i < 4; i++) qv[i] = Qs4[(rg * 4 + i) * 16 + (d4 ^ rg)];
#pragma unroll
            for (int j = 0; j < 4; j++) kv[j] = KP4[(cg * 4 + j) * 16 + (d4 ^ cg)];
#pragma unroll
            for (int i = 0; i < 4; i++)
#pragma unroll
                for (int j = 0; j < 4; j++)
                    s[i][j] += qv[i].x * kv[j].x + qv[i].y * kv[j].y +
                               qv[i].z * kv[j].z + qv[i].w * kv[j].w;
        }

#pragma unroll
        for (int i = 0; i < 4; i++)
#pragma unroll
            for (int j = 0; j < 4; j++) s[i][j] *= 0.125f;

        float pm[4];
#pragma unroll
        for (int i = 0; i < 4; i++)
            pm[i] = fmaxf(fmaxf(s[i][0], s[i][1]), fmaxf(s[i][2], s[i][3]));
#pragma unroll
        for (int off = 8; off; off >>= 1)
#pragma unroll
            for (int i = 0; i < 4; i++)
                pm[i] = fmaxf(pm[i], __shfl_xor_sync(0xffffffffu, pm[i], off, 32));

        float p[4][4], m_new[4], rs[4];
#pragma unroll
        for (int i = 0; i < 4; i++) {
            m_new[i] = fmaxf(m_i[i], pm[i]);
            rs[i] = 0.f;
#pragma unroll
            for (int j = 0; j < 4; j++) {
                p[i][j] = __expf(s[i][j] - m_new[i]);
                rs[i] += p[i][j];
            }
        }
#pragma unroll
        for (int off = 8; off; off >>= 1)
#pragma unroll
            for (int i = 0; i < 4; i++)
                rs[i] += __shfl_xor_sync(0xffffffffu, rs[i], off, 32);

#pragma unroll
        for (int i = 0; i < 4; i++) {
            const float alpha = __expf(m_i[i] - m_new[i]);
            l_i[i] = l_i[i] * alpha + rs[i];
            m_i[i] = m_new[i];
#pragma unroll
            for (int j = 0; j < 4; j++) o[i][j] *= alpha;
        }

        __syncthreads();
#pragma unroll
        for (int i = 0; i < 4; i++) {
            float4 pv = make_float4(p[i][0], p[i][1], p[i][2], p[i][3]);
            KP4[(rg * 4 + i) * 16 + (cg ^ rg)] = pv;
        }
        __syncthreads();

#pragma unroll
        for (int k4 = 0; k4 < 16; k4++) {
            float4 pp[4];
#pragma unroll
            for (int i = 0; i < 4; i++) pp[i] = KP4[(rg * 4 + i) * 16 + (k4 ^ rg)];
#pragma unroll
            for (int kk = 0; kk < 4; kk++) {
                float4 vrow = Vs4[(k4 * 4 + kk) * 16 + (cg ^ k4)];
#pragma unroll
                for (int i = 0; i < 4; i++) {
                    const float pi = ((const float*)&pp[i])[kk];
                    o[i][0] += pi * vrow.x;
                    o[i][1] += pi * vrow.y;
                    o[i][2] += pi * vrow.z;
                    o[i][3] += pi * vrow.w;
                }
            }
        }
    }

#pragma unroll
    for (int i = 0; i < 4; i++) {
        const float inv = 1.0f / l_i[i];
        float4 r = make_float4(o[i][0] * inv, o[i][1] * inv, o[i][2] * inv, o[i][3] * inv);
        const int q = q0 + rg * 4 + i;
        *(float4*)(Out + ((size_t)b * SEQ + q) * DMODEL + h * HDIM + cg * 4) = r;
    }
}

// ---------------------------------------------------------------------------
extern "C" void kernel_launch(void* const* d_in, const int* in_sizes, int n_in,
                              void* d_out, int out_size) {
    const float* q  = (const float*)d_in[0];
    const float* k  = (const float*)d_in[1];
    const float* v  = (const float*)d_in[2];
    const float* Wq = (const float*)d_in[3];
    const float* bq = (const float*)d_in[4];
    const float* Wk = (const float*)d_in[5];
    const float* bk = (const float*)d_in[6];
    const float* Wv = (const float*)d_in[7];
    const float* bv = (const float*)d_in[8];
    const float* Wo = (const float*)d_in[9];
    const float* bo = (const float*)d_in[10];
    float* out = (float*)d_out;

    float *gq, *gk, *gv, *ga;
    cudaGetSymbolAddress((void**)&gq, g_Q);
    cudaGetSymbolAddress((void**)&gk, g_K);
    cudaGetSymbolAddress((void**)&gv, g_V);
    cudaGetSymbolAddress((void**)&ga, g_attn);

    dim3 gemm_grid(DMODEL / 128, MTOT / 128);   // (8, 32)
    dim3 block(256);

    gemm_tf32_kernel<<<gemm_grid, block>>>(q, Wq, bq, gq, 0);
    gemm_tf32_kernel<<<gemm_grid, block>>>(k, Wk, bk, gk, 0);
    gemm_tf32_kernel<<<gemm_grid, block>>>(v, Wv, bv, gv, 0);

    dim3 attn_grid(SEQ / 64, NHEADS, BATCH);  // (32, 16, 2)
    attn_kernel<<<attn_grid, block>>>(gq, gk, gv, ga);

    gemm_tf32_kernel<<<gemm_grid, block>>>(ga, Wo, bo, out, 1);
}

// round 7
// speedup vs baseline: 3.0907x; 1.9830x over previous
#include <cuda_runtime.h>
#include <cuda_bf16.h>
#include <cstdint>

// Problem constants
#define BATCH   2
#define SEQ     2048
#define DMODEL  1024
#define NHEADS  16
#define HDIM    64
#define MTOT    (BATCH * SEQ)          // 4096

// Scratch (device globals; no allocations allowed)
__device__ float g_Q[BATCH * NHEADS * SEQ * HDIM];     // [b,h,s,d]  16 MB
__device__ float g_K[BATCH * NHEADS * SEQ * HDIM];
__device__ float g_V[BATCH * NHEADS * SEQ * HDIM];
__device__ float g_attn[MTOT * DMODEL];                // [b*s, h*d] 16 MB

__device__ __forceinline__ uint32_t f2tf32(float f) {
    uint32_t r;
    asm("cvt.rna.tf32.f32 %0, %1;" : "=r"(r) : "f"(f));
    return r;
}

#define MMA_TF32(C, A, B0, B1)                                              \
    asm volatile(                                                           \
        "mma.sync.aligned.m16n8k8.row.col.f32.tf32.tf32.f32 "               \
        "{%0,%1,%2,%3}, {%4,%5,%6,%7}, {%8,%9}, {%0,%1,%2,%3};"             \
        : "+f"((C)[0]), "+f"((C)[1]), "+f"((C)[2]), "+f"((C)[3])            \
        : "r"((A)[0]), "r"((A)[1]), "r"((A)[2]), "r"((A)[3]),               \
          "r"(B0), "r"(B1))

// ---------------------------------------------------------------------------
// tf32 tensor-core GEMM: out[m][n] = X[m][:] @ W[:][n] + bias[n]
// (unchanged from round 5: 128x128x16 tile, 8 warps, m16n8k8, double-buffered)
// ---------------------------------------------------------------------------
#define SA 20
#define SB 136

__global__ __launch_bounds__(256, 2) void gemm_tf32_kernel(
    const float* __restrict__ X, const float* __restrict__ W,
    const float* __restrict__ bias, float* __restrict__ out, int mode) {
    __shared__ uint32_t As[2][128][SA];   // [m][k]
    __shared__ uint32_t Bs[2][16][SB];    // [k][n]

    const int tid  = threadIdx.x;
    const int lane = tid & 31;
    const int warp = tid >> 5;
    const int g = lane >> 2;
    const int t = lane & 3;
    const int wm = (warp >> 1) * 32;
    const int wn = (warp & 1) * 64;
    const int m0 = blockIdx.y * 128;
    const int n0 = blockIdx.x * 128;

    const int am[2]  = { tid >> 2, (tid + 256) >> 2 };
    const int ak[2]  = { (tid & 3) * 4, (tid & 3) * 4 };
    const int bk[2]  = { tid >> 5, (tid + 256) >> 5 };
    const int bn[2]  = { (tid & 31) * 4, (tid & 31) * 4 };

    const float* Xp = X + (size_t)m0 * DMODEL;
    const float* Wp = W + n0;

    float c[2][8][4];
#pragma unroll
    for (int mt = 0; mt < 2; mt++)
#pragma unroll
        for (int ni = 0; ni < 8; ni++)
#pragma unroll
            for (int r = 0; r < 4; r++) c[mt][ni][r] = 0.f;

    float4 ra[2], rb[2];

#pragma unroll
    for (int i = 0; i < 2; i++) {
        ra[i] = *(const float4*)(Xp + (size_t)am[i] * DMODEL + ak[i]);
        rb[i] = *(const float4*)(Wp + (size_t)bk[i] * DMODEL + bn[i]);
    }
#pragma unroll
    for (int i = 0; i < 2; i++) {
        uint32_t* ap = &As[0][am[i]][ak[i]];
        ap[0] = f2tf32(ra[i].x); ap[1] = f2tf32(ra[i].y);
        ap[2] = f2tf32(ra[i].z); ap[3] = f2tf32(ra[i].w);
        uint32_t* bp = &Bs[0][bk[i]][bn[i]];
        bp[0] = f2tf32(rb[i].x); bp[1] = f2tf32(rb[i].y);
        bp[2] = f2tf32(rb[i].z); bp[3] = f2tf32(rb[i].w);
    }
    __syncthreads();

    int buf = 0;
    const int NITER = DMODEL / 16;   // 64
    for (int it = 0; it < NITER; it++) {
        const int k_next = (it + 1) * 16;
        if (it + 1 < NITER) {
#pragma unroll
            for (int i = 0; i < 2; i++) {
                ra[i] = *(const float4*)(Xp + (size_t)am[i] * DMODEL + k_next + ak[i]);
                rb[i] = *(const float4*)(Wp + (size_t)(k_next + bk[i]) * DMODEL + bn[i]);
            }
        }

#pragma unroll
        for (int ks = 0; ks < 2; ks++) {
            const int kk = ks * 8;
            uint32_t a[2][4];
#pragma unroll
            for (int mt = 0; mt < 2; mt++) {
                const int row = wm + mt * 16 + g;
                a[mt][0] = As[buf][row    ][kk + t];
                a[mt][1] = As[buf][row + 8][kk + t];
                a[mt][2] = As[buf][row    ][kk + t + 4];
                a[mt][3] = As[buf][row + 8][kk + t + 4];
            }
#pragma unroll
            for (int ni = 0; ni < 8; ni++) {
                const uint32_t b0 = Bs[buf][kk + t    ][wn + ni * 8 + g];
                const uint32_t b1 = Bs[buf][kk + t + 4][wn + ni * 8 + g];
#pragma unroll
                for (int mt = 0; mt < 2; mt++) {
                    MMA_TF32(c[mt][ni], a[mt], b0, b1);
                }
            }
        }

        if (it + 1 < NITER) {
            const int nb = buf ^ 1;
#pragma unroll
            for (int i = 0; i < 2; i++) {
                uint32_t* ap = &As[nb][am[i]][ak[i]];
                ap[0] = f2tf32(ra[i].x); ap[1] = f2tf32(ra[i].y);
                ap[2] = f2tf32(ra[i].z); ap[3] = f2tf32(ra[i].w);
                uint32_t* bp = &Bs[nb][bk[i]][bn[i]];
                bp[0] = f2tf32(rb[i].x); bp[1] = f2tf32(rb[i].y);
                bp[2] = f2tf32(rb[i].z); bp[3] = f2tf32(rb[i].w);
            }
            __syncthreads();
            buf = nb;
        }
    }

#pragma unroll
    for (int ni = 0; ni < 8; ni++) {
        const int col = n0 + wn + ni * 8 + 2 * t;
        const float2 bb = *(const float2*)(bias + col);
#pragma unroll
        for (int mt = 0; mt < 2; mt++) {
            const int row0 = m0 + wm + mt * 16 + g;
#pragma unroll
            for (int half = 0; half < 2; half++) {
                const int m = row0 + half * 8;
                float2 r;
                r.x = c[mt][ni][half * 2 + 0] + bb.x;
                r.y = c[mt][ni][half * 2 + 1] + bb.y;
                if (mode == 0) {
                    const int b = m >> 11, s = m & 2047;
                    const int h = col >> 6, d = col & 63;
                    *(float2*)(out + (((size_t)b * NHEADS + h) * SEQ + s) * HDIM + d) = r;
                } else {
                    *(float2*)(out + (size_t)m * DMODEL + col) = r;
                }
            }
        }
    }
}

// ---------------------------------------------------------------------------
// tf32 tensor-core flash attention.
// Block = 128 q-rows x (head, batch); 8 warps x 16 rows each (warp-local
// softmax: row lives in one lane quad -> 2 shfl_xor reduce, no smem stats).
// K smem stride 68 words (B-frag bank = 4g+t, conflict-free);
// V smem stride 72 words (B-frag bank = 8t+g, conflict-free).
// P: C-fragment -> A-fragment relayout entirely in registers via quad shfl.
// ---------------------------------------------------------------------------
#define BQ 128
#define BK 64
#define SKK 68
#define SKV 72

__global__ __launch_bounds__(256, 1) void attn_tf32_kernel(
    const float* __restrict__ Q, const float* __restrict__ K,
    const float* __restrict__ V, float* __restrict__ Out) {
    __shared__ uint32_t Ks[BK][SKK];   // [key][d] tf32
    __shared__ uint32_t Vs[BK][SKV];   // [key][d] tf32

    const int tid  = threadIdx.x;
    const int lane = tid & 31;
    const int warp = tid >> 5;
    const int g = lane >> 2;     // 0..7
    const int t = lane & 3;      // 0..3
    const int q0 = blockIdx.x * BQ;
    const int h  = blockIdx.y;
    const int b  = blockIdx.z;
    const size_t bh = (size_t)b * NHEADS + h;
    const float* Qb = Q + bh * SEQ * HDIM;
    const float* Kb = K + bh * SEQ * HDIM;
    const float* Vb = V + bh * SEQ * HDIM;

    // Q fragments (pre-scaled by 1/sqrt(64)), kept in registers for all iters
    uint32_t qa[8][4];
    {
        const float* Qw = Qb + (size_t)(q0 + warp * 16) * HDIM;
#pragma unroll
        for (int ks = 0; ks < 8; ks++) {
            qa[ks][0] = f2tf32(0.125f * Qw[g       * HDIM + 8 * ks + t]);
            qa[ks][1] = f2tf32(0.125f * Qw[(g + 8) * HDIM + 8 * ks + t]);
            qa[ks][2] = f2tf32(0.125f * Qw[g       * HDIM + 8 * ks + t + 4]);
            qa[ks][3] = f2tf32(0.125f * Qw[(g + 8) * HDIM + 8 * ks + t + 4]);
        }
    }

    float o[8][4];
#pragma unroll
    for (int ni = 0; ni < 8; ni++)
#pragma unroll
        for (int r = 0; r < 4; r++) o[ni][r] = 0.f;
    float m0 = -1e30f, m1 = -1e30f, l0 = 0.f, l1 = 0.f;

    const int qb = lane & ~3;             // quad base lane
    const int s0 = qb + (t >> 1);         // shfl src for cols t   (elem t&1)
    const int s1 = s0 + 2;                // shfl src for cols t+4

    for (int kt = 0; kt < SEQ; kt += BK) {
        __syncthreads();
        // Stage K/V tile, converting to tf32
#pragma unroll
        for (int i = 0; i < 4; i++) {
            const int idx = tid + i * 256;
            const int r  = idx >> 4;
            const int c4 = (idx & 15) * 4;
            float4 kv = *(const float4*)(Kb + (size_t)(kt + r) * HDIM + c4);
            uint4 ku = make_uint4(f2tf32(kv.x), f2tf32(kv.y), f2tf32(kv.z), f2tf32(kv.w));
            *(uint4*)&Ks[r][c4] = ku;
            float4 vv = *(const float4*)(Vb + (size_t)(kt + r) * HDIM + c4);
            uint4 vu = make_uint4(f2tf32(vv.x), f2tf32(vv.y), f2tf32(vv.z), f2tf32(vv.w));
            *(uint4*)&Vs[r][c4] = vu;
        }
        __syncthreads();

        // S = (Q/8) @ K^T  : per warp m16 x n64 x k64
        float c[8][4];
#pragma unroll
        for (int ni = 0; ni < 8; ni++) {
            c[ni][0] = c[ni][1] = c[ni][2] = c[ni][3] = 0.f;
            const uint32_t* kcol = &Ks[ni * 8 + g][0];
#pragma unroll
            for (int ks = 0; ks < 8; ks++) {
                const uint32_t b0 = kcol[8 * ks + t];
                const uint32_t b1 = kcol[8 * ks + t + 4];
                MMA_TF32(c[ni], qa[ks], b0, b1);
            }
        }

        // Online softmax (rows r0 = g, r1 = g+8 of this warp's 16 rows)
        float pm0 = c[0][0], pm1 = c[0][2];
#pragma unroll
        for (int ni = 0; ni < 8; ni++) {
            pm0 = fmaxf(pm0, fmaxf(c[ni][0], c[ni][1]));
            pm1 = fmaxf(pm1, fmaxf(c[ni][2], c[ni][3]));
        }
        pm0 = fmaxf(pm0, __shfl_xor_sync(0xffffffffu, pm0, 1));
        pm0 = fmaxf(pm0, __shfl_xor_sync(0xffffffffu, pm0, 2));
        pm1 = fmaxf(pm1, __shfl_xor_sync(0xffffffffu, pm1, 1));
        pm1 = fmaxf(pm1, __shfl_xor_sync(0xffffffffu, pm1, 2));

        const float mn0 = fmaxf(m0, pm0);
        const float mn1 = fmaxf(m1, pm1);
        float rs0 = 0.f, rs1 = 0.f;
#pragma unroll
        for (int ni = 0; ni < 8; ni++) {
            c[ni][0] = __expf(c[ni][0] - mn0);
            c[ni][1] = __expf(c[ni][1] - mn0);
            c[ni][2] = __expf(c[ni][2] - mn1);
            c[ni][3] = __expf(c[ni][3] - mn1);
            rs0 += c[ni][0] + c[ni][1];
            rs1 += c[ni][2] + c[ni][3];
        }
        rs0 += __shfl_xor_sync(0xffffffffu, rs0, 1);
        rs0 += __shfl_xor_sync(0xffffffffu, rs0, 2);
        rs1 += __shfl_xor_sync(0xffffffffu, rs1, 1);
        rs1 += __shfl_xor_sync(0xffffffffu, rs1, 2);

        const float alpha0 = __expf(m0 - mn0);
        const float alpha1 = __expf(m1 - mn1);
        l0 = l0 * alpha0 + rs0;  m0 = mn0;
        l1 = l1 * alpha1 + rs1;  m1 = mn1;
#pragma unroll
        for (int ni = 0; ni < 8; ni++) {
            o[ni][0] *= alpha0; o[ni][1] *= alpha0;
            o[ni][2] *= alpha1; o[ni][3] *= alpha1;
        }

        // Relayout P: C-fragment (cols 2t,2t+1) -> A-fragment (cols t, t+4)
        uint32_t pa[8][4];
#pragma unroll
        for (int j = 0; j < 8; j++) {
            const float v00 = __shfl_sync(0xffffffffu, c[j][0], s0);
            const float v01 = __shfl_sync(0xffffffffu, c[j][1], s0);
            const float v02 = __shfl_sync(0xffffffffu, c[j][0], s1);
            const float v03 = __shfl_sync(0xffffffffu, c[j][1], s1);
            const float v10 = __shfl_sync(0xffffffffu, c[j][2], s0);
            const float v11 = __shfl_sync(0xffffffffu, c[j][3], s0);
            const float v12 = __shfl_sync(0xffffffffu, c[j][2], s1);
            const float v13 = __shfl_sync(0xffffffffu, c[j][3], s1);
            pa[j][0] = f2tf32((t & 1) ? v01 : v00);   // row g,   col 8j+t
            pa[j][1] = f2tf32((t & 1) ? v11 : v10);   // row g+8, col 8j+t
            pa[j][2] = f2tf32((t & 1) ? v03 : v02);   // row g,   col 8j+t+4
            pa[j][3] = f2tf32((t & 1) ? v13 : v12);   // row g+8, col 8j+t+4
        }

        // O += P @ V : per warp m16 x n64 x k64
#pragma unroll
        for (int j = 0; j < 8; j++) {
#pragma unroll
            for (int ni = 0; ni < 8; ni++) {
                const uint32_t b0 = Vs[8 * j + t    ][ni * 8 + g];
                const uint32_t b1 = Vs[8 * j + t + 4][ni * 8 + g];
                MMA_TF32(o[ni], pa[j], b0, b1);
            }
        }
    }

    // Epilogue: normalize, write [b*s][h*64+d]
    const float inv0 = 1.0f / l0;
    const float inv1 = 1.0f / l1;
    const int r0 = q0 + warp * 16 + g;
    const int r1 = r0 + 8;
#pragma unroll
    for (int ni = 0; ni < 8; ni++) {
        const int col = h * HDIM + ni * 8 + 2 * t;
        float2 w0 = make_float2(o[ni][0] * inv0, o[ni][1] * inv0);
        float2 w1 = make_float2(o[ni][2] * inv1, o[ni][3] * inv1);
        *(float2*)(Out + ((size_t)b * SEQ + r0) * DMODEL + col) = w0;
        *(float2*)(Out + ((size_t)b * SEQ + r1) * DMODEL + col) = w1;
    }
}

// ---------------------------------------------------------------------------
extern "C" void kernel_launch(void* const* d_in, const int* in_sizes, int n_in,
                              void* d_out, int out_size) {
    const float* q  = (const float*)d_in[0];
    const float* k  = (const float*)d_in[1];
    const float* v  = (const float*)d_in[2];
    const float* Wq = (const float*)d_in[3];
    const float* bq = (const float*)d_in[4];
    const float* Wk = (const float*)d_in[5];
    const float* bk = (const float*)d_in[6];
    const float* Wv = (const float*)d_in[7];
    const float* bv = (const float*)d_in[8];
    const float* Wo = (const float*)d_in[9];
    const float* bo = (const float*)d_in[10];
    float* out = (float*)d_out;

    float *gq, *gk, *gv, *ga;
    cudaGetSymbolAddress((void**)&gq, g_Q);
    cudaGetSymbolAddress((void**)&gk, g_K);
    cudaGetSymbolAddress((void**)&gv, g_V);
    cudaGetSymbolAddress((void**)&ga, g_attn);

    dim3 gemm_grid(DMODEL / 128, MTOT / 128);   // (8, 32)
    dim3 block(256);

    gemm_tf32_kernel<<<gemm_grid, block>>>(q, Wq, bq, gq, 0);
    gemm_tf32_kernel<<<gemm_grid, block>>>(k, Wk, bk, gk, 0);
    gemm_tf32_kernel<<<gemm_grid, block>>>(v, Wv, bv, gv, 0);

    dim3 attn_grid(SEQ / BQ, NHEADS, BATCH);    // (16, 16, 2)
    attn_tf32_kernel<<<attn_grid, block>>>(gq, gk, gv, ga);

    gemm_tf32_kernel<<<gemm_grid, block>>>(ga, Wo, bo, out, 1);
}

// round 9
// speedup vs baseline: 3.3408x; 1.0809x over previous
#include <cuda_runtime.h>
#include <cuda_bf16.h>
#include <cstdint>

// Problem constants
#define BATCH   2
#define SEQ     2048
#define DMODEL  1024
#define NHEADS  16
#define HDIM    64
#define MTOT    (BATCH * SEQ)          // 4096

// Scratch (device globals; no allocations allowed)
__device__ float g_Q[BATCH * NHEADS * SEQ * HDIM];     // [b,h,s,d]  16 MB
__device__ float g_K[BATCH * NHEADS * SEQ * HDIM];
__device__ float g_V[BATCH * NHEADS * SEQ * HDIM];
__device__ float g_attn[MTOT * DMODEL];                // [b*s, h*d] 16 MB

__device__ __forceinline__ uint32_t f2tf32(float f) {
    uint32_t r;
    asm("cvt.rna.tf32.f32 %0, %1;" : "=r"(r) : "f"(f));
    return r;
}

#define MMA_TF32(C, A, B0, B1)                                              \
    asm volatile(                                                           \
        "mma.sync.aligned.m16n8k8.row.col.f32.tf32.tf32.f32 "               \
        "{%0,%1,%2,%3}, {%4,%5,%6,%7}, {%8,%9}, {%0,%1,%2,%3};"             \
        : "+f"((C)[0]), "+f"((C)[1]), "+f"((C)[2]), "+f"((C)[3])            \
        : "r"((A)[0]), "r"((A)[1]), "r"((A)[2]), "r"((A)[3]),               \
          "r"(B0), "r"(B1))

// ---------------------------------------------------------------------------
// tf32 tensor-core GEMM body: out[m][n] = X[m][:] @ W[:][n] + bias[n]
// 128x128x16 tile, 8 warps (4x2), warp 32x64 via m16n8k8, double-buffered.
// mode 0: scatter to head-major [b,h,s,d]; mode 1: row-major [m][n].
// ---------------------------------------------------------------------------
#define SA 20
#define SB 136

__device__ __forceinline__ void gemm_body(
    const float* __restrict__ X, const float* __restrict__ W,
    const float* __restrict__ bias, float* __restrict__ out, int mode) {
    __shared__ uint32_t As[2][128][SA];   // [m][k]
    __shared__ uint32_t Bs[2][16][SB];    // [k][n]

    const int tid  = threadIdx.x;
    const int lane = tid & 31;
    const int warp = tid >> 5;
    const int g = lane >> 2;
    const int t = lane & 3;
    const int wm = (warp >> 1) * 32;
    const int wn = (warp & 1) * 64;
    const int m0 = blockIdx.y * 128;
    const int n0 = blockIdx.x * 128;

    const int am[2]  = { tid >> 2, (tid + 256) >> 2 };
    const int ak[2]  = { (tid & 3) * 4, (tid & 3) * 4 };
    const int bk[2]  = { tid >> 5, (tid + 256) >> 5 };
    const int bn[2]  = { (tid & 31) * 4, (tid & 31) * 4 };

    const float* Xp = X + (size_t)m0 * DMODEL;
    const float* Wp = W + n0;

    float c[2][8][4];
#pragma unroll
    for (int mt = 0; mt < 2; mt++)
#pragma unroll
        for (int ni = 0; ni < 8; ni++)
#pragma unroll
            for (int r = 0; r < 4; r++) c[mt][ni][r] = 0.f;

    float4 ra[2], rb[2];

#pragma unroll
    for (int i = 0; i < 2; i++) {
        ra[i] = *(const float4*)(Xp + (size_t)am[i] * DMODEL + ak[i]);
        rb[i] = *(const float4*)(Wp + (size_t)bk[i] * DMODEL + bn[i]);
    }
#pragma unroll
    for (int i = 0; i < 2; i++) {
        uint32_t* ap = &As[0][am[i]][ak[i]];
        ap[0] = f2tf32(ra[i].x); ap[1] = f2tf32(ra[i].y);
        ap[2] = f2tf32(ra[i].z); ap[3] = f2tf32(ra[i].w);
        uint32_t* bp = &Bs[0][bk[i]][bn[i]];
        bp[0] = f2tf32(rb[i].x); bp[1] = f2tf32(rb[i].y);
        bp[2] = f2tf32(rb[i].z); bp[3] = f2tf32(rb[i].w);
    }
    __syncthreads();

    int buf = 0;
    const int NITER = DMODEL / 16;   // 64
    for (int it = 0; it < NITER; it++) {
        const int k_next = (it + 1) * 16;
        if (it + 1 < NITER) {
#pragma unroll
            for (int i = 0; i < 2; i++) {
                ra[i] = *(const float4*)(Xp + (size_t)am[i] * DMODEL + k_next + ak[i]);
                rb[i] = *(const float4*)(Wp + (size_t)(k_next + bk[i]) * DMODEL + bn[i]);
            }
        }

#pragma unroll
        for (int ks = 0; ks < 2; ks++) {
            const int kk = ks * 8;
            uint32_t a[2][4];
#pragma unroll
            for (int mt = 0; mt < 2; mt++) {
                const int row = wm + mt * 16 + g;
                a[mt][0] = As[buf][row    ][kk + t];
                a[mt][1] = As[buf][row + 8][kk + t];
                a[mt][2] = As[buf][row    ][kk + t + 4];
                a[mt][3] = As[buf][row + 8][kk + t + 4];
            }
#pragma unroll
            for (int ni = 0; ni < 8; ni++) {
                const uint32_t b0 = Bs[buf][kk + t    ][wn + ni * 8 + g];
                const uint32_t b1 = Bs[buf][kk + t + 4][wn + ni * 8 + g];
#pragma unroll
                for (int mt = 0; mt < 2; mt++) {
                    MMA_TF32(c[mt][ni], a[mt], b0, b1);
                }
            }
        }

        if (it + 1 < NITER) {
            const int nb = buf ^ 1;
#pragma unroll
            for (int i = 0; i < 2; i++) {
                uint32_t* ap = &As[nb][am[i]][ak[i]];
                ap[0] = f2tf32(ra[i].x); ap[1] = f2tf32(ra[i].y);
                ap[2] = f2tf32(ra[i].z); ap[3] = f2tf32(ra[i].w);
                uint32_t* bp = &Bs[nb][bk[i]][bn[i]];
                bp[0] = f2tf32(rb[i].x); bp[1] = f2tf32(rb[i].y);
                bp[2] = f2tf32(rb[i].z); bp[3] = f2tf32(rb[i].w);
            }
            __syncthreads();
            buf = nb;
        }
    }

#pragma unroll
    for (int ni = 0; ni < 8; ni++) {
        const int col = n0 + wn + ni * 8 + 2 * t;
        const float2 bb = *(const float2*)(bias + col);
#pragma unroll
        for (int mt = 0; mt < 2; mt++) {
            const int row0 = m0 + wm + mt * 16 + g;
#pragma unroll
            for (int half = 0; half < 2; half++) {
                const int m = row0 + half * 8;
                float2 r;
                r.x = c[mt][ni][half * 2 + 0] + bb.x;
                r.y = c[mt][ni][half * 2 + 1] + bb.y;
                if (mode == 0) {
                    const int b = m >> 11, s = m & 2047;
                    const int h = col >> 6, d = col & 63;
                    *(float2*)(out + (((size_t)b * NHEADS + h) * SEQ + s) * HDIM + d) = r;
                } else {
                    *(float2*)(out + (size_t)m * DMODEL + col) = r;
                }
            }
        }
    }
}

__global__ __launch_bounds__(256, 2) void gemm_tf32_kernel(
    const float* __restrict__ X, const float* __restrict__ W,
    const float* __restrict__ bias, float* __restrict__ out, int mode) {
    gemm_body(X, W, bias, out, mode);
}

// Fused Q/K/V projections: blockIdx.z selects operand set (one launch, 768 CTAs)
__global__ __launch_bounds__(256, 2) void gemm_qkv_kernel(
    const float* __restrict__ xq, const float* __restrict__ xk, const float* __restrict__ xv,
    const float* __restrict__ Wq, const float* __restrict__ Wk, const float* __restrict__ Wv,
    const float* __restrict__ bq, const float* __restrict__ bk, const float* __restrict__ bv,
    float* __restrict__ oq, float* __restrict__ ok, float* __restrict__ ov) {
    const int z = blockIdx.z;
    const float* X = (z == 0) ? xq : (z == 1) ? xk : xv;
    const float* W = (z == 0) ? Wq : (z == 1) ? Wk : Wv;
    const float* B = (z == 0) ? bq : (z == 1) ? bk : bv;
    float*       O = (z == 0) ? oq : (z == 1) ? ok : ov;
    gemm_body(X, W, B, O, 0);
}

// ---------------------------------------------------------------------------
// tf32 tensor-core flash attention, software-pipelined K/V prefetch.
// Block = 128 q-rows x (head, batch); 8 warps x 16 rows each, warp-local
// softmax (2 shfl_xor per stat). K stride 68, V stride 72 (conflict-free).
// P: C-frag -> A-frag relayout in registers via quad shfl.
// Next tile's K/V LDGs are issued before compute so DRAM latency overlaps
// the ~128 MMAs of the current tile.
// ---------------------------------------------------------------------------
#define BQ 128
#define BK 64
#define SKK 68
#define SKV 72

__global__ __launch_bounds__(256, 1) void attn_tf32_kernel(
    const float* __restrict__ Q, const float* __restrict__ K,
    const float* __restrict__ V, float* __restrict__ Out) {
    __shared__ uint32_t Ks[BK][SKK];   // [key][d] tf32
    __shared__ uint32_t Vs[BK][SKV];   // [key][d] tf32

    const int tid  = threadIdx.x;
    const int lane = tid & 31;
    const int warp = tid >> 5;
    const int g = lane >> 2;     // 0..7
    const int t = lane & 3;      // 0..3
    const int q0 = blockIdx.x * BQ;
    const int h  = blockIdx.y;
    const int b  = blockIdx.z;
    const size_t bh = (size_t)b * NHEADS + h;
    const float* Qb = Q + bh * SEQ * HDIM;
    const float* Kb = K + bh * SEQ * HDIM;
    const float* Vb = V + bh * SEQ * HDIM;

    // Staging-load coords (4 chunks of 256 threads)
    const int sr[4] = { tid >> 4, (tid + 256) >> 4, (tid + 512) >> 4, (tid + 768) >> 4 };
    const int sc    = (tid & 15) * 4;

    // Q fragments (pre-scaled by 1/sqrt(64)), in registers for all iterations
    uint32_t qa[8][4];
    {
        const float* Qw = Qb + (size_t)(q0 + warp * 16) * HDIM;
#pragma unroll
        for (int ks = 0; ks < 8; ks++) {
            qa[ks][0] = f2tf32(0.125f * Qw[g       * HDIM + 8 * ks + t]);
            qa[ks][1] = f2tf32(0.125f * Qw[(g + 8) * HDIM + 8 * ks + t]);
            qa[ks][2] = f2tf32(0.125f * Qw[g       * HDIM + 8 * ks + t + 4]);
            qa[ks][3] = f2tf32(0.125f * Qw[(g + 8) * HDIM + 8 * ks + t + 4]);
        }
    }

    float o[8][4];
#pragma unroll
    for (int ni = 0; ni < 8; ni++)
#pragma unroll
        for (int r = 0; r < 4; r++) o[ni][r] = 0.f;
    float m0 = -1e30f, m1 = -1e30f, l0 = 0.f, l1 = 0.f;

    const int qb = lane & ~3;             // quad base lane
    const int s0 = qb + (t >> 1);         // shfl src for cols t   (elem t&1)
    const int s1 = s0 + 2;                // shfl src for cols t+4

    // Prefetch tile 0 into registers
    float4 kpre[4], vpre[4];
#pragma unroll
    for (int i = 0; i < 4; i++) {
        kpre[i] = *(const float4*)(Kb + (size_t)sr[i] * HDIM + sc);
        vpre[i] = *(const float4*)(Vb + (size_t)sr[i] * HDIM + sc);
    }

    for (int kt = 0; kt < SEQ; kt += BK) {
        __syncthreads();   // prior iteration done reading smem
        // Commit prefetched tile to smem (cvt to tf32 on the fill path)
#pragma unroll
        for (int i = 0; i < 4; i++) {
            uint4 ku = make_uint4(f2tf32(kpre[i].x), f2tf32(kpre[i].y),
                                  f2tf32(kpre[i].z), f2tf32(kpre[i].w));
            *(uint4*)&Ks[sr[i]][sc] = ku;
            uint4 vu = make_uint4(f2tf32(vpre[i].x), f2tf32(vpre[i].y),
                                  f2tf32(vpre[i].z), f2tf32(vpre[i].w));
            *(uint4*)&Vs[sr[i]][sc] = vu;
        }
        __syncthreads();

        // Issue next tile's LDGs now — latency overlaps the MMAs below
        if (kt + BK < SEQ) {
            const float* Kn = Kb + (size_t)(kt + BK) * HDIM;
            const float* Vn = Vb + (size_t)(kt + BK) * HDIM;
#pragma unroll
            for (int i = 0; i < 4; i++) {
                kpre[i] = *(const float4*)(Kn + (size_t)sr[i] * HDIM + sc);
                vpre[i] = *(const float4*)(Vn + (size_t)sr[i] * HDIM + sc);
            }
        }

        // S = (Q/8) @ K^T  : per warp m16 x n64 x k64
        float c[8][4];
#pragma unroll
        for (int ni = 0; ni < 8; ni++) {
            c[ni][0] = c[ni][1] = c[ni][2] = c[ni][3] = 0.f;
            const uint32_t* kcol = &Ks[ni * 8 + g][0];
#pragma unroll
            for (int ks = 0; ks < 8; ks++) {
                const uint32_t b0 = kcol[8 * ks + t];
                const uint32_t b1 = kcol[8 * ks + t + 4];
                MMA_TF32(c[ni], qa[ks], b0, b1);
            }
        }

        // Online softmax (rows r0 = g, r1 = g+8 of this warp's 16 rows)
        float pm0 = c[0][0], pm1 = c[0][2];
#pragma unroll
        for (int ni = 0; ni < 8; ni++) {
            pm0 = fmaxf(pm0, fmaxf(c[ni][0], c[ni][1]));
            pm1 = fmaxf(pm1, fmaxf(c[ni][2], c[ni][3]));
        }
        pm0 = fmaxf(pm0, __shfl_xor_sync(0xffffffffu, pm0, 1));
        pm0 = fmaxf(pm0, __shfl_xor_sync(0xffffffffu, pm0, 2));
        pm1 = fmaxf(pm1, __shfl_xor_sync(0xffffffffu, pm1, 1));
        pm1 = fmaxf(pm1, __shfl_xor_sync(0xffffffffu, pm1, 2));

        const float mn0 = fmaxf(m0, pm0);
        const float mn1 = fmaxf(m1, pm1);
        float rs0 = 0.f, rs1 = 0.f;
#pragma unroll
        for (int ni = 0; ni < 8; ni++) {
            c[ni][0] = __expf(c[ni][0] - mn0);
            c[ni][1] = __expf(c[ni][1] - mn0);
            c[ni][2] = __expf(c[ni][2] - mn1);
            c[ni][3] = __expf(c[ni][3] - mn1);
            rs0 += c[ni][0] + c[ni][1];
            rs1 += c[ni][2] + c[ni][3];
        }
        rs0 += __shfl_xor_sync(0xffffffffu, rs0, 1);
        rs0 += __shfl_xor_sync(0xffffffffu, rs0, 2);
        rs1 += __shfl_xor_sync(0xffffffffu, rs1, 1);
        rs1 += __shfl_xor_sync(0xffffffffu, rs1, 2);

        const float alpha0 = __expf(m0 - mn0);
        const float alpha1 = __expf(m1 - mn1);
        l0 = l0 * alpha0 + rs0;  m0 = mn0;
        l1 = l1 * alpha1 + rs1;  m1 = mn1;
#pragma unroll
        for (int ni = 0; ni < 8; ni++) {
            o[ni][0] *= alpha0; o[ni][1] *= alpha0;
            o[ni][2] *= alpha1; o[ni][3] *= alpha1;
        }

        // Relayout P: C-fragment (cols 2t,2t+1) -> A-fragment (cols t, t+4)
        uint32_t pa[8][4];
#pragma unroll
        for (int j = 0; j < 8; j++) {
            const float v00 = __shfl_sync(0xffffffffu, c[j][0], s0);
            const float v01 = __shfl_sync(0xffffffffu, c[j][1], s0);
            const float v02 = __shfl_sync(0xffffffffu, c[j][0], s1);
            const float v03 = __shfl_sync(0xffffffffu, c[j][1], s1);
            const float v10 = __shfl_sync(0xffffffffu, c[j][2], s0);
            const float v11 = __shfl_sync(0xffffffffu, c[j][3], s0);
            const float v12 = __shfl_sync(0xffffffffu, c[j][2], s1);
            const float v13 = __shfl_sync(0xffffffffu, c[j][3], s1);
            pa[j][0] = f2tf32((t & 1) ? v01 : v00);   // row g,   col 8j+t
            pa[j][1] = f2tf32((t & 1) ? v11 : v10);   // row g+8, col 8j+t
            pa[j][2] = f2tf32((t & 1) ? v03 : v02);   // row g,   col 8j+t+4
            pa[j][3] = f2tf32((t & 1) ? v13 : v12);   // row g+8, col 8j+t+4
        }

        // O += P @ V : per warp m16 x n64 x k64
#pragma unroll
        for (int j = 0; j < 8; j++) {
#pragma unroll
            for (int ni = 0; ni < 8; ni++) {
                const uint32_t b0 = Vs[8 * j + t    ][ni * 8 + g];
                const uint32_t b1 = Vs[8 * j + t + 4][ni * 8 + g];
                MMA_TF32(o[ni], pa[j], b0, b1);
            }
        }
    }

    // Epilogue: normalize, write [b*s][h*64+d]
    const float inv0 = 1.0f / l0;
    const float inv1 = 1.0f / l1;
    const int r0 = q0 + warp * 16 + g;
    const int r1 = r0 + 8;
#pragma unroll
    for (int ni = 0; ni < 8; ni++) {
        const int col = h * HDIM + ni * 8 + 2 * t;
        float2 w0 = make_float2(o[ni][0] * inv0, o[ni][1] * inv0);
        float2 w1 = make_float2(o[ni][2] * inv1, o[ni][3] * inv1);
        *(float2*)(Out + ((size_t)b * SEQ + r0) * DMODEL + col) = w0;
        *(float2*)(Out + ((size_t)b * SEQ + r1) * DMODEL + col) = w1;
    }
}

// ---------------------------------------------------------------------------
extern "C" void kernel_launch(void* const* d_in, const int* in_sizes, int n_in,
                              void* d_out, int out_size) {
    const float* q  = (const float*)d_in[0];
    const float* k  = (const float*)d_in[1];
    const float* v  = (const float*)d_in[2];
    const float* Wq = (const float*)d_in[3];
    const float* bq = (const float*)d_in[4];
    const float* Wk = (const float*)d_in[5];
    const float* bk = (const float*)d_in[6];
    const float* Wv = (const float*)d_in[7];
    const float* bv = (const float*)d_in[8];
    const float* Wo = (const float*)d_in[9];
    const float* bo = (const float*)d_in[10];
    float* out = (float*)d_out;

    float *gq, *gk, *gv, *ga;
    cudaGetSymbolAddress((void**)&gq, g_Q);
    cudaGetSymbolAddress((void**)&gk, g_K);
    cudaGetSymbolAddress((void**)&gv, g_V);
    cudaGetSymbolAddress((void**)&ga, g_attn);

    dim3 block(256);

    // Fused Q/K/V projections: one launch, grid (8, 32, 3)
    dim3 qkv_grid(DMODEL / 128, MTOT / 128, 3);
    gemm_qkv_kernel<<<qkv_grid, block>>>(q, k, v, Wq, Wk, Wv, bq, bk, bv, gq, gk, gv);

    dim3 attn_grid(SEQ / BQ, NHEADS, BATCH);    // (16, 16, 2)
    attn_tf32_kernel<<<attn_grid, block>>>(gq, gk, gv, ga);

    dim3 gemm_grid(DMODEL / 128, MTOT / 128);   // (8, 32)
    gemm_tf32_kernel<<<gemm_grid, block>>>(ga, Wo, bo, out, 1);
}

// round 10
// speedup vs baseline: 3.5903x; 1.0747x over previous
#include <cuda_runtime.h>
#include <cuda_bf16.h>
#include <cstdint>

// Problem constants
#define BATCH   2
#define SEQ     2048
#define DMODEL  1024
#define NHEADS  16
#define HDIM    64
#define MTOT    (BATCH * SEQ)          // 4096

// Scratch (device globals; no allocations allowed)
// Q/K/V hold tf32-rounded fp32 bit patterns (written by projection epilogue).
__device__ float g_Q[BATCH * NHEADS * SEQ * HDIM];     // [b,h,s,d]  16 MB
__device__ float g_K[BATCH * NHEADS * SEQ * HDIM];
__device__ float g_V[BATCH * NHEADS * SEQ * HDIM];
__device__ float g_attn[MTOT * DMODEL];                // [b*s, h*d] 16 MB

__device__ __forceinline__ uint32_t f2tf32(float f) {
    uint32_t r;
    asm("cvt.rna.tf32.f32 %0, %1;" : "=r"(r) : "f"(f));
    return r;
}

#define MMA_TF32(C, A, B0, B1)                                              \
    asm volatile(                                                           \
        "mma.sync.aligned.m16n8k8.row.col.f32.tf32.tf32.f32 "               \
        "{%0,%1,%2,%3}, {%4,%5,%6,%7}, {%8,%9}, {%0,%1,%2,%3};"             \
        : "+f"((C)[0]), "+f"((C)[1]), "+f"((C)[2]), "+f"((C)[3])            \
        : "r"((A)[0]), "r"((A)[1]), "r"((A)[2]), "r"((A)[3]),               \
          "r"(B0), "r"(B1))

#define CP_ASYNC16(dst, src)                                                \
    asm volatile("cp.async.ca.shared.global [%0], [%1], 16;"                \
                 :: "r"(dst), "l"(src))
#define CP_COMMIT()  asm volatile("cp.async.commit_group;" ::: "memory")
#define CP_WAIT(n)   asm volatile("cp.async.wait_group %0;" :: "n"(n) : "memory")

// ---------------------------------------------------------------------------
// tf32 tensor-core GEMM body: out[m][n] = X[m][:] @ W[:][n] + bias[n]
// 128x128x16 tile, 8 warps (4x2), warp 32x64 via m16n8k8, double-buffered.
// mode 0: scatter to head-major [b,h,s,d], value tf32-ROUNDED (consumer is
//         the attention kernel, which uses raw bits as mma operands);
// mode 1: plain row-major [m][n], full fp32 (final output).
// ---------------------------------------------------------------------------
#define SA 20
#define SB 136

__device__ __forceinline__ void gemm_body(
    const float* __restrict__ X, const float* __restrict__ W,
    const float* __restrict__ bias, float* __restrict__ out, int mode) {
    __shared__ uint32_t As[2][128][SA];   // [m][k]
    __shared__ uint32_t Bs[2][16][SB];    // [k][n]

    const int tid  = threadIdx.x;
    const int lane = tid & 31;
    const int warp = tid >> 5;
    const int g = lane >> 2;
    const int t = lane & 3;
    const int wm = (warp >> 1) * 32;
    const int wn = (warp & 1) * 64;
    const int m0 = blockIdx.y * 128;
    const int n0 = blockIdx.x * 128;

    const int am[2]  = { tid >> 2, (tid + 256) >> 2 };
    const int ak[2]  = { (tid & 3) * 4, (tid & 3) * 4 };
    const int bk[2]  = { tid >> 5, (tid + 256) >> 5 };
    const int bn[2]  = { (tid & 31) * 4, (tid & 31) * 4 };

    const float* Xp = X + (size_t)m0 * DMODEL;
    const float* Wp = W + n0;

    float c[2][8][4];
#pragma unroll
    for (int mt = 0; mt < 2; mt++)
#pragma unroll
        for (int ni = 0; ni < 8; ni++)
#pragma unroll
            for (int r = 0; r < 4; r++) c[mt][ni][r] = 0.f;

    float4 ra[2], rb[2];

#pragma unroll
    for (int i = 0; i < 2; i++) {
        ra[i] = *(const float4*)(Xp + (size_t)am[i] * DMODEL + ak[i]);
        rb[i] = *(const float4*)(Wp + (size_t)bk[i] * DMODEL + bn[i]);
    }
#pragma unroll
    for (int i = 0; i < 2; i++) {
        uint32_t* ap = &As[0][am[i]][ak[i]];
        ap[0] = f2tf32(ra[i].x); ap[1] = f2tf32(ra[i].y);
        ap[2] = f2tf32(ra[i].z); ap[3] = f2tf32(ra[i].w);
        uint32_t* bp = &Bs[0][bk[i]][bn[i]];
        bp[0] = f2tf32(rb[i].x); bp[1] = f2tf32(rb[i].y);
        bp[2] = f2tf32(rb[i].z); bp[3] = f2tf32(rb[i].w);
    }
    __syncthreads();

    int buf = 0;
    const int NITER = DMODEL / 16;   // 64
    for (int it = 0; it < NITER; it++) {
        const int k_next = (it + 1) * 16;
        if (it + 1 < NITER) {
#pragma unroll
            for (int i = 0; i < 2; i++) {
                ra[i] = *(const float4*)(Xp + (size_t)am[i] * DMODEL + k_next + ak[i]);
                rb[i] = *(const float4*)(Wp + (size_t)(k_next + bk[i]) * DMODEL + bn[i]);
            }
        }

#pragma unroll
        for (int ks = 0; ks < 2; ks++) {
            const int kk = ks * 8;
            uint32_t a[2][4];
#pragma unroll
            for (int mt = 0; mt < 2; mt++) {
                const int row = wm + mt * 16 + g;
                a[mt][0] = As[buf][row    ][kk + t];
                a[mt][1] = As[buf][row + 8][kk + t];
                a[mt][2] = As[buf][row    ][kk + t + 4];
                a[mt][3] = As[buf][row + 8][kk + t + 4];
            }
#pragma unroll
            for (int ni = 0; ni < 8; ni++) {
                const uint32_t b0 = Bs[buf][kk + t    ][wn + ni * 8 + g];
                const uint32_t b1 = Bs[buf][kk + t + 4][wn + ni * 8 + g];
#pragma unroll
                for (int mt = 0; mt < 2; mt++) {
                    MMA_TF32(c[mt][ni], a[mt], b0, b1);
                }
            }
        }

        if (it + 1 < NITER) {
            const int nb = buf ^ 1;
#pragma unroll
            for (int i = 0; i < 2; i++) {
                uint32_t* ap = &As[nb][am[i]][ak[i]];
                ap[0] = f2tf32(ra[i].x); ap[1] = f2tf32(ra[i].y);
                ap[2] = f2tf32(ra[i].z); ap[3] = f2tf32(ra[i].w);
                uint32_t* bp = &Bs[nb][bk[i]][bn[i]];
                bp[0] = f2tf32(rb[i].x); bp[1] = f2tf32(rb[i].y);
                bp[2] = f2tf32(rb[i].z); bp[3] = f2tf32(rb[i].w);
            }
            __syncthreads();
            buf = nb;
        }
    }

#pragma unroll
    for (int ni = 0; ni < 8; ni++) {
        const int col = n0 + wn + ni * 8 + 2 * t;
        const float2 bb = *(const float2*)(bias + col);
#pragma unroll
        for (int mt = 0; mt < 2; mt++) {
            const int row0 = m0 + wm + mt * 16 + g;
#pragma unroll
            for (int half = 0; half < 2; half++) {
                const int m = row0 + half * 8;
                float2 r;
                r.x = c[mt][ni][half * 2 + 0] + bb.x;
                r.y = c[mt][ni][half * 2 + 1] + bb.y;
                if (mode == 0) {
                    // tf32-round at write: consumer (attn) uses bits directly
                    r.x = __uint_as_float(f2tf32(r.x));
                    r.y = __uint_as_float(f2tf32(r.y));
                    const int b = m >> 11, s = m & 2047;
                    const int h = col >> 6, d = col & 63;
                    *(float2*)(out + (((size_t)b * NHEADS + h) * SEQ + s) * HDIM + d) = r;
                } else {
                    *(float2*)(out + (size_t)m * DMODEL + col) = r;
                }
            }
        }
    }
}

__global__ __launch_bounds__(256, 2) void gemm_tf32_kernel(
    const float* __restrict__ X, const float* __restrict__ W,
    const float* __restrict__ bias, float* __restrict__ out, int mode) {
    gemm_body(X, W, bias, out, mode);
}

// Fused Q/K/V projections: blockIdx.z selects operand set (one launch, 768 CTAs)
__global__ __launch_bounds__(256, 2) void gemm_qkv_kernel(
    const float* __restrict__ xq, const float* __restrict__ xk, const float* __restrict__ xv,
    const float* __restrict__ Wq, const float* __restrict__ Wk, const float* __restrict__ Wv,
    const float* __restrict__ bq, const float* __restrict__ bk, const float* __restrict__ bv,
    float* __restrict__ oq, float* __restrict__ ok, float* __restrict__ ov) {
    const int z = blockIdx.z;
    const float* X = (z == 0) ? xq : (z == 1) ? xk : xv;
    const float* W = (z == 0) ? Wq : (z == 1) ? Wk : Wv;
    const float* B = (z == 0) ? bq : (z == 1) ? bk : bv;
    float*       O = (z == 0) ? oq : (z == 1) ? ok : ov;
    gemm_body(X, W, B, O, 0);
}

// ---------------------------------------------------------------------------
// tf32 tensor-core flash attention, cp.async double-buffered K/V pipeline.
// Block = 64 q-rows x (head, batch); 128 threads (4 warps x 16 rows),
// 3 CTAs/SM (12 warps/SM). K/V arrive in gmem already tf32-rounded, so
// staging is a pure 16B cp.async copy — no cvt, no register round-trip.
// K stride 68 / V stride 72 keep fragment reads conflict-free.
// Softmax warp-local (2 shfl_xor per stat); P relayout via quad shfl.
// ---------------------------------------------------------------------------
#define BQ 64
#define BK 64
#define SKK 68
#define SKV 72
#define KW   (BK * SKK)          // 4352 words per K stage
#define VW   (BK * SKV)          // 4608 words per V stage
#define STAGEW (KW + VW)         // 8960 words per stage
#define ATTN_SMEM_BYTES (2 * STAGEW * 4)   // 71680

extern __shared__ uint32_t dsm[];

__global__ __launch_bounds__(128, 3) void attn_tf32_kernel(
    const float* __restrict__ Q, const float* __restrict__ K,
    const float* __restrict__ V, float* __restrict__ Out) {
    const int tid  = threadIdx.x;
    const int lane = tid & 31;
    const int warp = tid >> 5;
    const int g = lane >> 2;     // 0..7
    const int t = lane & 3;      // 0..3
    const int q0 = blockIdx.x * BQ;
    const int h  = blockIdx.y;
    const int b  = blockIdx.z;
    const size_t bh = (size_t)b * NHEADS + h;
    const float* Qb = Q + bh * SEQ * HDIM;
    const float* Kb = K + bh * SEQ * HDIM;
    const float* Vb = V + bh * SEQ * HDIM;

    // Q fragments: gmem holds tf32 bits; x0.125 (power of two) is exact and
    // keeps the value tf32-representable -> use bits directly as mma operand.
    uint32_t qa[8][4];
    {
        const float* Qw = Qb + (size_t)(q0 + warp * 16) * HDIM;
#pragma unroll
        for (int ks = 0; ks < 8; ks++) {
            qa[ks][0] = __float_as_uint(0.125f * Qw[g       * HDIM + 8 * ks + t]);
            qa[ks][1] = __float_as_uint(0.125f * Qw[(g + 8) * HDIM + 8 * ks + t]);
            qa[ks][2] = __float_as_uint(0.125f * Qw[g       * HDIM + 8 * ks + t + 4]);
            qa[ks][3] = __float_as_uint(0.125f * Qw[(g + 8) * HDIM + 8 * ks + t + 4]);
        }
    }

    float o[8][4];
#pragma unroll
    for (int ni = 0; ni < 8; ni++)
#pragma unroll
        for (int r = 0; r < 4; r++) o[ni][r] = 0.f;
    float m0 = -1e30f, m1 = -1e30f, l0 = 0.f, l1 = 0.f;

    const int qb = lane & ~3;             // quad base lane
    const int s0 = qb + (t >> 1);         // shfl src for cols t   (elem t&1)
    const int s1 = s0 + 2;                // shfl src for cols t+4

    // cp.async staging: 128 threads x 16 chunks of 16B cover K + V tile
    // chunk i of 8: row = (tid + i*128)>>4, col4 = (tid&15)*4
    auto stage_tile = [&](int stage, int kt) {
        uint32_t* sK = dsm + stage * STAGEW;
        uint32_t* sV = sK + KW;
        const float* Kg = Kb + (size_t)kt * HDIM;
        const float* Vg = Vb + (size_t)kt * HDIM;
#pragma unroll
        for (int i = 0; i < 8; i++) {
            const int idx = tid + i * 128;
            const int r  = idx >> 4;
            const int c4 = (idx & 15) * 4;
            unsigned dk = (unsigned)__cvta_generic_to_shared(&sK[r * SKK + c4]);
            CP_ASYNC16(dk, Kg + (size_t)r * HDIM + c4);
            unsigned dv = (unsigned)__cvta_generic_to_shared(&sV[r * SKV + c4]);
            CP_ASYNC16(dv, Vg + (size_t)r * HDIM + c4);
        }
    };

    stage_tile(0, 0);
    CP_COMMIT();

    int buf = 0;
    for (int kt = 0; kt < SEQ; kt += BK) {
        if (kt + BK < SEQ) {
            stage_tile(buf ^ 1, kt + BK);
            CP_COMMIT();
            CP_WAIT(1);     // tile for this iteration complete
        } else {
            CP_WAIT(0);
        }
        __syncthreads();

        const uint32_t* sK = dsm + buf * STAGEW;
        const uint32_t* sV = sK + KW;

        // S = (Q/8) @ K^T  : per warp m16 x n64 x k64
        float c[8][4];
#pragma unroll
        for (int ni = 0; ni < 8; ni++) {
            c[ni][0] = c[ni][1] = c[ni][2] = c[ni][3] = 0.f;
            const uint32_t* kcol = &sK[(ni * 8 + g) * SKK];
#pragma unroll
            for (int ks = 0; ks < 8; ks++) {
                const uint32_t b0 = kcol[8 * ks + t];
                const uint32_t b1 = kcol[8 * ks + t + 4];
                MMA_TF32(c[ni], qa[ks], b0, b1);
            }
        }

        // Online softmax (rows r0 = g, r1 = g+8 of this warp's 16 rows)
        float pm0 = c[0][0], pm1 = c[0][2];
#pragma unroll
        for (int ni = 0; ni < 8; ni++) {
            pm0 = fmaxf(pm0, fmaxf(c[ni][0], c[ni][1]));
            pm1 = fmaxf(pm1, fmaxf(c[ni][2], c[ni][3]));
        }
        pm0 = fmaxf(pm0, __shfl_xor_sync(0xffffffffu, pm0, 1));
        pm0 = fmaxf(pm0, __shfl_xor_sync(0xffffffffu, pm0, 2));
        pm1 = fmaxf(pm1, __shfl_xor_sync(0xffffffffu, pm1, 1));
        pm1 = fmaxf(pm1, __shfl_xor_sync(0xffffffffu, pm1, 2));

        const float mn0 = fmaxf(m0, pm0);
        const float mn1 = fmaxf(m1, pm1);
        float rs0 = 0.f, rs1 = 0.f;
#pragma unroll
        for (int ni = 0; ni < 8; ni++) {
            c[ni][0] = __expf(c[ni][0] - mn0);
            c[ni][1] = __expf(c[ni][1] - mn0);
            c[ni][2] = __expf(c[ni][2] - mn1);
            c[ni][3] = __expf(c[ni][3] - mn1);
            rs0 += c[ni][0] + c[ni][1];
            rs1 += c[ni][2] + c[ni][3];
        }
        rs0 += __shfl_xor_sync(0xffffffffu, rs0, 1);
        rs0 += __shfl_xor_sync(0xffffffffu, rs0, 2);
        rs1 += __shfl_xor_sync(0xffffffffu, rs1, 1);
        rs1 += __shfl_xor_sync(0xffffffffu, rs1, 2);

        const float alpha0 = __expf(m0 - mn0);
        const float alpha1 = __expf(m1 - mn1);
        l0 = l0 * alpha0 + rs0;  m0 = mn0;
        l1 = l1 * alpha1 + rs1;  m1 = mn1;
#pragma unroll
        for (int ni = 0; ni < 8; ni++) {
            o[ni][0] *= alpha0; o[ni][1] *= alpha0;
            o[ni][2] *= alpha1; o[ni][3] *= alpha1;
        }

        // Relayout P: C-fragment (cols 2t,2t+1) -> A-fragment (cols t, t+4)
        uint32_t pa[8][4];
#pragma unroll
        for (int j = 0; j < 8; j++) {
            const float v00 = __shfl_sync(0xffffffffu, c[j][0], s0);
            const float v01 = __shfl_sync(0xffffffffu, c[j][1], s0);
            const float v02 = __shfl_sync(0xffffffffu, c[j][0], s1);
            const float v03 = __shfl_sync(0xffffffffu, c[j][1], s1);
            const float v10 = __shfl_sync(0xffffffffu, c[j][2], s0);
            const float v11 = __shfl_sync(0xffffffffu, c[j][3], s0);
            const float v12 = __shfl_sync(0xffffffffu, c[j][2], s1);
            const float v13 = __shfl_sync(0xffffffffu, c[j][3], s1);
            pa[j][0] = f2tf32((t & 1) ? v01 : v00);   // row g,   col 8j+t
            pa[j][1] = f2tf32((t & 1) ? v11 : v10);   // row g+8, col 8j+t
            pa[j][2] = f2tf32((t & 1) ? v03 : v02);   // row g,   col 8j+t+4
            pa[j][3] = f2tf32((t & 1) ? v13 : v12);   // row g+8, col 8j+t+4
        }

        // O += P @ V : per warp m16 x n64 x k64
#pragma unroll
        for (int j = 0; j < 8; j++) {
#pragma unroll
            for (int ni = 0; ni < 8; ni++) {
                const uint32_t b0 = sV[(8 * j + t    ) * SKV + ni * 8 + g];
                const uint32_t b1 = sV[(8 * j + t + 4) * SKV + ni * 8 + g];
                MMA_TF32(o[ni], pa[j], b0, b1);
            }
        }

        __syncthreads();   // all reads of buf done before it becomes a cp.async target
        buf ^= 1;
    }

    // Epilogue: normalize, write [b*s][h*64+d]
    const float inv0 = 1.0f / l0;
    const float inv1 = 1.0f / l1;
    const int r0 = q0 + warp * 16 + g;
    const int r1 = r0 + 8;
#pragma unroll
    for (int ni = 0; ni < 8; ni++) {
        const int col = h * HDIM + ni * 8 + 2 * t;
        float2 w0 = make_float2(o[ni][0] * inv0, o[ni][1] * inv0);
        float2 w1 = make_float2(o[ni][2] * inv1, o[ni][3] * inv1);
        *(float2*)(Out + ((size_t)b * SEQ + r0) * DMODEL + col) = w0;
        *(float2*)(Out + ((size_t)b * SEQ + r1) * DMODEL + col) = w1;
    }
}

// ---------------------------------------------------------------------------
extern "C" void kernel_launch(void* const* d_in, const int* in_sizes, int n_in,
                              void* d_out, int out_size) {
    const float* q  = (const float*)d_in[0];
    const float* k  = (const float*)d_in[1];
    const float* v  = (const float*)d_in[2];
    const float* Wq = (const float*)d_in[3];
    const float* bq = (const float*)d_in[4];
    const float* Wk = (const float*)d_in[5];
    const float* bk = (const float*)d_in[6];
    const float* Wv = (const float*)d_in[7];
    const float* bv = (const float*)d_in[8];
    const float* Wo = (const float*)d_in[9];
    const float* bo = (const float*)d_in[10];
    float* out = (float*)d_out;

    float *gq, *gk, *gv, *ga;
    cudaGetSymbolAddress((void**)&gq, g_Q);
    cudaGetSymbolAddress((void**)&gk, g_K);
    cudaGetSymbolAddress((void**)&gv, g_V);
    cudaGetSymbolAddress((void**)&ga, g_attn);

    static bool attr_done = false;
    if (!attr_done) {
        cudaFuncSetAttribute(attn_tf32_kernel,
                             cudaFuncAttributeMaxDynamicSharedMemorySize,
                             ATTN_SMEM_BYTES);
        attr_done = true;
    }

    // Fused Q/K/V projections: one launch, grid (8, 32, 3)
    dim3 qkv_grid(DMODEL / 128, MTOT / 128, 3);
    gemm_qkv_kernel<<<qkv_grid, dim3(256)>>>(q, k, v, Wq, Wk, Wv, bq, bk, bv, gq, gk, gv);

    dim3 attn_grid(SEQ / BQ, NHEADS, BATCH);    // (32, 16, 2) = 1024 CTAs
    attn_tf32_kernel<<<attn_grid, dim3(128), ATTN_SMEM_BYTES>>>(gq, gk, gv, ga);

    dim3 gemm_grid(DMODEL / 128, MTOT / 128);   // (8, 32)
    gemm_tf32_kernel<<<gemm_grid, dim3(256)>>>(ga, Wo, bo, out, 1);
}